// round 12
// baseline (speedup 1.0000x reference)
#include <cuda_runtime.h>
#include <cuda_fp16.h>
#include <cstdint>

#define SEQ   64
#define BATCH 64
#define EMBD  512
#define HID   1024
#define VOCAB 32000
#define SB    (SEQ*BATCH)
#define H3    (3*HID)

// ---------------- device scratch ----------------
__device__ __half g_E[SB*EMBD];
__device__ __half g_wih[H3*EMBD];
__device__ __half g_wout[(size_t)VOCAB*HID];
__device__ float  g_gi[(size_t)SB*H3];
__device__ __half g_hs[(size_t)SB*HID];
__device__ __half g_h16[2][BATCH*HID];
__device__ volatile int g_flag = 0;
__device__ volatile unsigned g_pcount = 0;
__device__ unsigned g_gcnt[8*64];          // group counters, 256B apart
__device__ unsigned g_rootc = 0;

// ---------------- ptx helpers ----------------
__device__ __forceinline__ uint32_t smem_u32(const void* p){
    return (uint32_t)__cvta_generic_to_shared(p);
}
__device__ __forceinline__ void ldsm_x4(uint32_t&a0,uint32_t&a1,uint32_t&a2,uint32_t&a3,uint32_t addr){
    asm volatile("ldmatrix.sync.aligned.m8n8.x4.shared.b16 {%0,%1,%2,%3},[%4];"
                 :"=r"(a0),"=r"(a1),"=r"(a2),"=r"(a3):"r"(addr));
}
__device__ __forceinline__ void ldsm_x2(uint32_t&b0,uint32_t&b1,uint32_t addr){
    asm volatile("ldmatrix.sync.aligned.m8n8.x2.shared.b16 {%0,%1},[%2];"
                 :"=r"(b0),"=r"(b1):"r"(addr));
}
__device__ __forceinline__ void mma16816(float&d0,float&d1,float&d2,float&d3,
                                         uint32_t a0,uint32_t a1,uint32_t a2,uint32_t a3,
                                         uint32_t b0,uint32_t b1){
    asm volatile("mma.sync.aligned.m16n8k16.row.col.f32.f16.f16.f32 "
                 "{%0,%1,%2,%3},{%4,%5,%6,%7},{%8,%9},{%0,%1,%2,%3};"
                 :"+f"(d0),"+f"(d1),"+f"(d2),"+f"(d3)
                 :"r"(a0),"r"(a1),"r"(a2),"r"(a3),"r"(b0),"r"(b1));
}
__device__ __forceinline__ void cp16(uint32_t saddr, const void* g){
    asm volatile("cp.async.cg.shared.global [%0],[%1],16;"::"r"(saddr),"l"(g));
}
__device__ __forceinline__ void cp_commit(){ asm volatile("cp.async.commit_group;"); }
template<int N> __device__ __forceinline__ void cp_wait(){ asm volatile("cp.async.wait_group %0;"::"n"(N)); }

// ---------------- prep kernels ----------------
__global__ void k_cvt(const float* __restrict__ src, __half* __restrict__ dst, int n2){
    int i = blockIdx.x*blockDim.x + threadIdx.x;
    if (i < n2){
        float2 v = reinterpret_cast<const float2*>(src)[i];
        reinterpret_cast<__half2*>(dst)[i] = __floats2half2_rn(v.x, v.y);
    }
}
__global__ void k_embed(const int* __restrict__ x, const float* __restrict__ emb){
    int i = blockIdx.x*blockDim.x + threadIdx.x;
    if (i >= SB*EMBD/2) return;
    int row = i/(EMBD/2), cp = i%(EMBD/2);
    int s = row>>6, b = row&63;
    int tok = (s==0) ? 2 : x[(s-1)*BATCH + b];
    float2 v = reinterpret_cast<const float2*>(emb + (size_t)tok*EMBD)[cp];
    float a0 = (tok==0)?0.f:fmaxf(v.x,0.f);
    float a1 = (tok==0)?0.f:fmaxf(v.y,0.f);
    reinterpret_cast<__half2*>(g_E)[i] = __floats2half2_rn(a0, a1);
}
__global__ void k_inith(const float* __restrict__ hidden){
    int i = blockIdx.x*blockDim.x + threadIdx.x;
    if (i < BATCH*HID) g_h16[0][i] = __float2half(hidden[i]);
    if (i < 8*64) g_gcnt[i] = 0;
    if (i == 0){ g_flag = 0; g_pcount = 0; g_rootc = 0; }
}

// ---------------- gi GEMM (cp.async HMMA, BM=BN=128, BK=64, occ2, 2-stage) ----------------
#define GBM 128
#define GBN 128
#define GBK 64
#define ROWB 144
#define STG_ROWS (GBM+GBN)           // 256
#define STG_BYTES (STG_ROWS*ROWB)    // 36864
#define G_SMEM (2*STG_BYTES)         // 73728

__global__ __launch_bounds__(256,2)
void k_gemm(const __half* __restrict__ A, const __half* __restrict__ Bw,
            const float* __restrict__ bias, float* __restrict__ C, int K, int N){
    extern __shared__ char smem[];
    uint32_t sbase = smem_u32(smem);
    int tid = threadIdx.x;
    int bm = blockIdx.x, bn = blockIdx.y;
    const __half* Ab = A + (size_t)bm*GBM*K;
    const __half* Bb = Bw + (size_t)bn*GBN*K;

    int NK = K/GBK;
    auto load_stage = [&](int i){
        uint32_t stg = sbase + (i&1)*STG_BYTES;
        #pragma unroll
        for (int t=0;t<8;t++){
            int c = tid + t*256;
            int row = c>>3, c16 = c&7;
            const __half* src = (row < GBM)
                ? (Ab + (size_t)row*K + i*GBK + c16*8)
                : (Bb + (size_t)(row-GBM)*K + i*GBK + c16*8);
            cp16(stg + row*ROWB + c16*16, src);
        }
        cp_commit();
    };
    load_stage(0); load_stage(1);

    int warp = tid>>5, lane = tid&31;
    int wm = warp&1, wn = warp>>1;
    float acc[4][4][4];
    #pragma unroll
    for(int mi=0;mi<4;mi++) for(int ni=0;ni<4;ni++) for(int d=0;d<4;d++) acc[mi][ni][d]=0.f;

    for (int i=0; i<NK; i++){
        if (i <= NK-2) cp_wait<1>(); else cp_wait<0>();
        __syncthreads();
        uint32_t sA = sbase + (i&1)*STG_BYTES;
        uint32_t sB = sA + GBM*ROWB;
        #pragma unroll
        for (int k16=0; k16<GBK/16; k16++){
            uint32_t a[4][4], b[2][4];
            #pragma unroll
            for(int mi=0;mi<4;mi++){
                int row = wm*64 + mi*16 + (lane&15);
                int col = (k16*16 + (lane>>4)*8)*2;
                ldsm_x4(a[mi][0],a[mi][1],a[mi][2],a[mi][3], sA + row*ROWB + col);
            }
            #pragma unroll
            for(int nj=0;nj<2;nj++){
                int row = wn*32 + nj*16 + ((lane>>4)*8) + (lane&7);
                int col = (k16*16 + ((lane>>3)&1)*8)*2;
                ldsm_x4(b[nj][0],b[nj][1],b[nj][2],b[nj][3], sB + row*ROWB + col);
            }
            #pragma unroll
            for(int mi=0;mi<4;mi++)
                #pragma unroll
                for(int nj=0;nj<2;nj++){
                    mma16816(acc[mi][2*nj][0],acc[mi][2*nj][1],acc[mi][2*nj][2],acc[mi][2*nj][3],
                             a[mi][0],a[mi][1],a[mi][2],a[mi][3], b[nj][0],b[nj][1]);
                    mma16816(acc[mi][2*nj+1][0],acc[mi][2*nj+1][1],acc[mi][2*nj+1][2],acc[mi][2*nj+1][3],
                             a[mi][0],a[mi][1],a[mi][2],a[mi][3], b[nj][2],b[nj][3]);
                }
        }
        __syncthreads();
        if (i + 2 < NK) load_stage(i + 2);
    }

    int mbase = bm*GBM + wm*64;
    int nbase = bn*GBN + wn*32;
    #pragma unroll
    for(int mi=0;mi<4;mi++){
        int r0 = mbase + mi*16 + (lane>>2);
        #pragma unroll
        for(int ni=0;ni<4;ni++){
            int cc = nbase + ni*8 + 2*(lane&3);
            float bv0 = bias[cc], bv1 = bias[cc+1];
            *reinterpret_cast<float2*>(C + (size_t)r0*N + cc) =
                make_float2(acc[mi][ni][0]+bv0, acc[mi][ni][1]+bv1);
            *reinterpret_cast<float2*>(C + (size_t)(r0+8)*N + cc) =
                make_float2(acc[mi][ni][2]+bv0, acc[mi][ni][3]+bv1);
        }
    }
}

// ---------------- fused recurrence + projection ----------------
#define RECUR_CTAS 128
#define PROJ_CTAS  168
#define TOT_CTAS   (RECUR_CTAS+PROJ_CTAS)
#define NT_BM      (SB/GBM)            // 32
#define NT_BN      (VOCAB/GBN)         // 250
#define NT_TILES   (NT_BM*NT_BN)       // 8000
#define P_SPLIT    4800
#define PSTAGE     3
#define F_SMEM     (PSTAGE*STG_BYTES)  // 110592
#define WOUT_N2    ((int)((size_t)VOCAB*HID/2))

__device__ __forceinline__ void proj_tile(uint32_t sbase, int bm, int bn, int tid,
                                          const __half* __restrict__ Apool,
                                          const __half* __restrict__ Bw,
                                          const float* __restrict__ bias,
                                          float* __restrict__ C){
    const __half* Ab = Apool + (size_t)bm*GBM*HID;
    const __half* Bb = Bw + (size_t)bn*GBN*HID;
    const int NK = HID/GBK;  // 16
    auto load_stage = [&](int i){
        uint32_t stg = sbase + (i%PSTAGE)*STG_BYTES;
        #pragma unroll
        for (int t=0;t<8;t++){
            int c = tid + t*256;
            int row = c>>3, c16 = c&7;
            const __half* src = (row < GBM)
                ? (Ab + (size_t)row*HID + i*GBK + c16*8)
                : (Bb + (size_t)(row-GBM)*HID + i*GBK + c16*8);
            cp16(stg + row*ROWB + c16*16, src);
        }
        cp_commit();
    };
    load_stage(0); load_stage(1); load_stage(2);

    int warp = tid>>5, lane = tid&31;
    int wm = warp&1, wn = warp>>1;
    float acc[4][4][4];
    #pragma unroll
    for(int mi=0;mi<4;mi++) for(int ni=0;ni<4;ni++) for(int d=0;d<4;d++) acc[mi][ni][d]=0.f;

    for (int i=0; i<NK; i++){
        if      (i <= NK-3) cp_wait<2>();
        else if (i == NK-2) cp_wait<1>();
        else                cp_wait<0>();
        __syncthreads();
        uint32_t sA = sbase + (i%PSTAGE)*STG_BYTES;
        uint32_t sB = sA + GBM*ROWB;
        #pragma unroll
        for (int k16=0; k16<GBK/16; k16++){
            uint32_t a[4][4], b[2][4];
            #pragma unroll
            for(int mi=0;mi<4;mi++){
                int row = wm*64 + mi*16 + (lane&15);
                int col = (k16*16 + (lane>>4)*8)*2;
                ldsm_x4(a[mi][0],a[mi][1],a[mi][2],a[mi][3], sA + row*ROWB + col);
            }
            #pragma unroll
            for(int nj=0;nj<2;nj++){
                int row = wn*32 + nj*16 + ((lane>>4)*8) + (lane&7);
                int col = (k16*16 + ((lane>>3)&1)*8)*2;
                ldsm_x4(b[nj][0],b[nj][1],b[nj][2],b[nj][3], sB + row*ROWB + col);
            }
            #pragma unroll
            for(int mi=0;mi<4;mi++)
                #pragma unroll
                for(int nj=0;nj<2;nj++){
                    mma16816(acc[mi][2*nj][0],acc[mi][2*nj][1],acc[mi][2*nj][2],acc[mi][2*nj][3],
                             a[mi][0],a[mi][1],a[mi][2],a[mi][3], b[nj][0],b[nj][1]);
                    mma16816(acc[mi][2*nj+1][0],acc[mi][2*nj+1][1],acc[mi][2*nj+1][2],acc[mi][2*nj+1][3],
                             a[mi][0],a[mi][1],a[mi][2],a[mi][3], b[nj][2],b[nj][3]);
                }
        }
        __syncthreads();
        if (i + PSTAGE < NK) load_stage(i + PSTAGE);
    }

    int mbase = bm*GBM + wm*64;
    int nbase = bn*GBN + wn*32;
    #pragma unroll
    for(int mi=0;mi<4;mi++){
        int r0 = mbase + mi*16 + (lane>>2);
        #pragma unroll
        for(int ni=0;ni<4;ni++){
            int cc = nbase + ni*8 + 2*(lane&3);
            float bv0 = bias[cc], bv1 = bias[cc+1];
            int rr = r0;
            size_t ro = (size_t)((rr&63)*64 + (rr>>6))*VOCAB;
            *reinterpret_cast<float2*>(C + ro + cc) = make_float2(acc[mi][ni][0]+bv0, acc[mi][ni][1]+bv1);
            rr = r0+8;
            ro = (size_t)((rr&63)*64 + (rr>>6))*VOCAB;
            *reinterpret_cast<float2*>(C + ro + cc) = make_float2(acc[mi][ni][2]+bv0, acc[mi][ni][3]+bv1);
        }
    }
}

__device__ __forceinline__ void wait_flag(int need, int tid){
    if (tid == 0){
        while (g_flag < need) __nanosleep(128);
        __threadfence();
    }
    __syncthreads();
}
__device__ __forceinline__ void wait_pcount(int tid){
    if (tid == 0){
        while (g_pcount < PROJ_CTAS) __nanosleep(128);
        __threadfence();
    }
    __syncthreads();
}

__global__ __launch_bounds__(256,2)
void k_fused(const float* __restrict__ w_hh, const float* __restrict__ b_hh,
             const float* __restrict__ hidden,
             const float* __restrict__ w_out_f32, const float* __restrict__ b_out,
             float* __restrict__ out){
    extern __shared__ char smem[];
    uint32_t sbase = smem_u32(smem);
    int tid = threadIdx.x;
    int cta = blockIdx.x;

    if (cta < RECUR_CTAS){
        // ===== recurrence: j-slice [cta*8, cta*8+8) =====
        __half* sW  = (__half*)smem;                    // 24 x 1032 halfs
        __half* sH  = (__half*)(smem + 49536);          // 64 x 136 halfs
        float*  sGH = (float*)(smem + 66944);           // 64 x 24 f32
        int j0 = cta*8;

        for (int idx = tid; idx < 24*HID; idx += 256){
            int r = idx>>10, k = idx&1023;
            int g = r>>3, jr = r&7;
            sW[r*1032 + k] = __float2half(w_hh[(size_t)(g*HID + j0 + jr)*HID + k]);
        }
        float bh0[2], bh1[2], bh2[2], hold[2];
        #pragma unroll
        for (int t=0;t<2;t++){
            int o = tid + t*256; int b = o>>3, jj = o&7; int j = j0+jj;
            bh0[t]=b_hh[j]; bh1[t]=b_hh[HID+j]; bh2[t]=b_hh[2*HID+j];
            hold[t]=hidden[b*HID + j];
        }
        int warp = tid>>5, lane = tid&31;
        int wm = warp&3, wn = warp>>2;
        int nacc = (wn==0)?2:1;
        __syncthreads();

        for (int s=0; s<SEQ; s++){
            const __half* hb = g_h16[s&1];
            float acc[2][4];
            #pragma unroll
            for(int q=0;q<2;q++) for(int d=0;d<4;d++) acc[q][d]=0.f;

            for (int ch=0; ch<8; ch++){
                __syncthreads();
                #pragma unroll
                for (int i=0;i<4;i++){
                    int lin = tid + i*256;
                    int row = lin>>4, c8 = lin&15;
                    uint4 v = __ldcg(reinterpret_cast<const uint4*>(hb + row*HID + ch*128 + c8*8));
                    *reinterpret_cast<uint4*>(&sH[row*136 + c8*8]) = v;
                }
                __syncthreads();
                #pragma unroll
                for (int k16=0;k16<8;k16++){
                    uint32_t a0,a1,a2,a3;
                    int arow = wm*16 + (lane&15);
                    int acol = k16*16 + (lane>>4)*8;
                    ldsm_x4(a0,a1,a2,a3, smem_u32(&sH[arow*136 + acol]));
                    #pragma unroll
                    for (int q=0;q<2;q++){
                        if (q < nacc){
                            int ni = wn*2 + q;
                            uint32_t b0,b1;
                            int brow = ni*8 + (lane&7);
                            int bcol = ch*128 + k16*16 + ((lane>>3)&1)*8;
                            ldsm_x2(b0,b1, smem_u32(&sW[brow*1032 + bcol]));
                            mma16816(acc[q][0],acc[q][1],acc[q][2],acc[q][3],a0,a1,a2,a3,b0,b1);
                        }
                    }
                }
            }
            {
                int r = wm*16 + (lane>>2);
                #pragma unroll
                for (int q=0;q<2;q++){
                    if (q < nacc){
                        int ni = wn*2 + q;
                        int cc = ni*8 + 2*(lane&3);
                        sGH[r*24 + cc]       = acc[q][0];
                        sGH[r*24 + cc+1]     = acc[q][1];
                        sGH[(r+8)*24 + cc]   = acc[q][2];
                        sGH[(r+8)*24 + cc+1] = acc[q][3];
                    }
                }
            }
            __syncthreads();
            __half* hwr = g_h16[(s+1)&1];
            #pragma unroll
            for (int t=0;t<2;t++){
                int o = tid + t*256; int b = o>>3, jj = o&7; int j = j0+jj;
                const float* gi = g_gi + (size_t)(s*BATCH + b)*H3;
                float ir = gi[j], iz = gi[HID+j], inn = gi[2*HID+j];
                float hr = sGH[b*24+jj]    + bh0[t];
                float hz = sGH[b*24+8+jj]  + bh1[t];
                float hn = sGH[b*24+16+jj] + bh2[t];
                float rg = 1.f/(1.f+__expf(-(ir+hr)));
                float zg = 1.f/(1.f+__expf(-(iz+hz)));
                float ng = tanhf(inn + rg*hn);
                float hnew = (1.f - zg)*ng + zg*hold[t];
                hold[t] = hnew;
                unsigned short hb16 = __half_as_ushort(__float2half(hnew));
                __stcg(reinterpret_cast<unsigned short*>(hwr + b*HID + j), hb16);
                __stcg(reinterpret_cast<unsigned short*>(g_hs + (size_t)(s*BATCH + b)*HID + j), hb16);
            }
            // ---- two-level monotonic grid barrier (8 groups x 16) ----
            __threadfence();
            __syncthreads();
            if (tid==0){
                unsigned a = atomicAdd(&g_gcnt[(cta&7)*64], 1u);
                if (a == 16u*(unsigned)(s+1) - 1u){
                    unsigned r = atomicAdd(&g_rootc, 1u);
                    if (r == 8u*(unsigned)(s+1) - 1u){
                        __threadfence();
                        g_flag = s+1;
                    }
                }
                while (g_flag < s+1) __nanosleep(32);
                __threadfence();
            }
            __syncthreads();
        }
        // ===== tail projection tiles (after wout cvt done) =====
        wait_pcount(tid);
        for (int t = P_SPLIT + cta; t < NT_TILES; t += RECUR_CTAS){
            int bm = t / NT_BN, bn = t % NT_BN;
            proj_tile(sbase, bm, bn, tid, g_hs, g_wout, b_out, out);
        }
    } else {
        // ===== projection CTAs: first convert w_out to fp16, then gated tiles =====
        int pidx = cta - RECUR_CTAS;
        {
            const float2* src = reinterpret_cast<const float2*>(w_out_f32);
            __half2* dst = reinterpret_cast<__half2*>(g_wout);
            for (int i = pidx*256 + tid; i < WOUT_N2; i += PROJ_CTAS*256){
                float2 v = src[i];
                dst[i] = __floats2half2_rn(v.x, v.y);
            }
        }
        __threadfence();
        __syncthreads();
        if (tid == 0) atomicAdd((unsigned*)&g_pcount, 1u);
        wait_pcount(tid);

        for (int t = pidx; t < P_SPLIT; t += PROJ_CTAS){
            int bm = t / NT_BN, bn = t % NT_BN;
            wait_flag(2*bm + 2, tid);
            proj_tile(sbase, bm, bn, tid, g_hs, g_wout, b_out, out);
        }
    }
}

// ---------------- launch ----------------
extern "C" void kernel_launch(void* const* d_in, const int* in_sizes, int n_in,
                              void* d_out, int out_size){
    const int*   x      = (const int*)  d_in[0];
    const float* hidden = (const float*)d_in[1];
    const float* emb    = (const float*)d_in[2];
    const float* w_ih   = (const float*)d_in[3];
    const float* w_hh   = (const float*)d_in[4];
    const float* b_ih   = (const float*)d_in[5];
    const float* b_hh   = (const float*)d_in[6];
    const float* w_out  = (const float*)d_in[7];
    const float* b_out  = (const float*)d_in[8];
    float* out = (float*)d_out;

    __half *pE, *pWih;
    float  *pGi;
    cudaGetSymbolAddress((void**)&pE,    g_E);
    cudaGetSymbolAddress((void**)&pWih,  g_wih);
    cudaGetSymbolAddress((void**)&pGi,   g_gi);

    cudaFuncSetAttribute(k_gemm,  cudaFuncAttributeMaxDynamicSharedMemorySize, G_SMEM);
    cudaFuncSetAttribute(k_fused, cudaFuncAttributeMaxDynamicSharedMemorySize, F_SMEM);

    {   int n2 = H3*EMBD/2;
        k_cvt<<<(n2+255)/256,256>>>(w_ih, pWih, n2); }
    k_embed<<<(SB*EMBD/2+255)/256,256>>>(x, emb);
    k_inith<<<(BATCH*HID+255)/256,256>>>(hidden);

    // gi = relu(E) @ w_ih^T + b_ih   (4096 x 3072, K=512)
    k_gemm<<<dim3(SB/GBM, H3/GBN), 256, G_SMEM>>>(pE, pWih, b_ih, pGi, EMBD, H3);

    // fused: recurrence + wout-cvt + projection
    k_fused<<<TOT_CTAS, 256, F_SMEM>>>(w_hh, b_hh, hidden, w_out, b_out, out);
}

// round 15
// speedup vs baseline: 1.2074x; 1.2074x over previous
#include <cuda_runtime.h>
#include <cuda_fp16.h>
#include <cstdint>

#define SEQ   64
#define BATCH 64
#define EMBD  512
#define HID   1024
#define VOCAB 32000
#define SB    (SEQ*BATCH)
#define H3    (3*HID)

// ---------------- device scratch ----------------
__device__ __half g_E[SB*EMBD];
__device__ __half g_wih[H3*EMBD];
__device__ __half g_wout[(size_t)VOCAB*HID];
__device__ float  g_gi[(size_t)SB*H3];
__device__ __half g_hs[(size_t)SB*HID];
__device__ __half g_h16[2][BATCH*HID];
__device__ unsigned g_bar_count = 0;
__device__ volatile unsigned g_bar_sense = 0;
__device__ volatile int g_flag = 0;
__device__ volatile unsigned g_pcount = 0;
__device__ unsigned g_ticket = 0;

// ---------------- ptx helpers ----------------
__device__ __forceinline__ uint32_t smem_u32(const void* p){
    return (uint32_t)__cvta_generic_to_shared(p);
}
__device__ __forceinline__ void ldsm_x4(uint32_t&a0,uint32_t&a1,uint32_t&a2,uint32_t&a3,uint32_t addr){
    asm volatile("ldmatrix.sync.aligned.m8n8.x4.shared.b16 {%0,%1,%2,%3},[%4];"
                 :"=r"(a0),"=r"(a1),"=r"(a2),"=r"(a3):"r"(addr));
}
__device__ __forceinline__ void ldsm_x2(uint32_t&b0,uint32_t&b1,uint32_t addr){
    asm volatile("ldmatrix.sync.aligned.m8n8.x2.shared.b16 {%0,%1},[%2];"
                 :"=r"(b0),"=r"(b1):"r"(addr));
}
__device__ __forceinline__ void mma16816(float&d0,float&d1,float&d2,float&d3,
                                         uint32_t a0,uint32_t a1,uint32_t a2,uint32_t a3,
                                         uint32_t b0,uint32_t b1){
    asm volatile("mma.sync.aligned.m16n8k16.row.col.f32.f16.f16.f32 "
                 "{%0,%1,%2,%3},{%4,%5,%6,%7},{%8,%9},{%0,%1,%2,%3};"
                 :"+f"(d0),"+f"(d1),"+f"(d2),"+f"(d3)
                 :"r"(a0),"r"(a1),"r"(a2),"r"(a3),"r"(b0),"r"(b1));
}
__device__ __forceinline__ void cp16(uint32_t saddr, const void* g){
    asm volatile("cp.async.cg.shared.global [%0],[%1],16;"::"r"(saddr),"l"(g));
}
__device__ __forceinline__ void cp_commit(){ asm volatile("cp.async.commit_group;"); }
template<int N> __device__ __forceinline__ void cp_wait(){ asm volatile("cp.async.wait_group %0;"::"n"(N)); }

// ---------------- merged prep kernel ----------------
// Grid MUST cover the LARGEST task: embed = SB*EMBD/2 = 1,048,576 threads
// (R13/R14 bug: grid sized for w_ih cvt = 786,432 -> g_E rows for s>=48 never written).
__global__ void k_prep(const int* __restrict__ x, const float* __restrict__ emb,
                       const float* __restrict__ w_ih, const float* __restrict__ hidden){
    int i = blockIdx.x*blockDim.x + threadIdx.x;
    if (i < H3*EMBD/2){
        float2 v = reinterpret_cast<const float2*>(w_ih)[i];
        reinterpret_cast<__half2*>(g_wih)[i] = __floats2half2_rn(v.x, v.y);
    }
    if (i < SB*EMBD/2){
        int row = i/(EMBD/2), cp = i%(EMBD/2);
        int s = row>>6, b = row&63;
        int tok = (s==0) ? 2 : x[(s-1)*BATCH + b];
        float2 v = reinterpret_cast<const float2*>(emb + (size_t)tok*EMBD)[cp];
        float a0 = (tok==0)?0.f:fmaxf(v.x,0.f);
        float a1 = (tok==0)?0.f:fmaxf(v.y,0.f);
        reinterpret_cast<__half2*>(g_E)[i] = __floats2half2_rn(a0, a1);
    }
    if (i < BATCH*HID) g_h16[0][i] = __float2half(hidden[i]);
    if (i == 0){ g_bar_count = 0; g_bar_sense = 0; g_flag = 0; g_pcount = 0; g_ticket = 0; }
}

// ---------------- gi GEMM (cp.async HMMA, BM=BN=128, BK=64, occ2, 2-stage) ----------------
#define GBM 128
#define GBN 128
#define GBK 64
#define ROWB 144
#define STG_ROWS (GBM+GBN)           // 256
#define STG_BYTES (STG_ROWS*ROWB)    // 36864
#define G_SMEM (2*STG_BYTES)         // 73728

__global__ __launch_bounds__(256,2)
void k_gemm(const __half* __restrict__ A, const __half* __restrict__ Bw,
            const float* __restrict__ bias, float* __restrict__ C, int K, int N){
    extern __shared__ char smem[];
    uint32_t sbase = smem_u32(smem);
    int tid = threadIdx.x;
    int bm = blockIdx.x, bn = blockIdx.y;
    const __half* Ab = A + (size_t)bm*GBM*K;
    const __half* Bb = Bw + (size_t)bn*GBN*K;

    int NK = K/GBK;
    auto load_stage = [&](int i){
        uint32_t stg = sbase + (i&1)*STG_BYTES;
        #pragma unroll
        for (int t=0;t<8;t++){
            int c = tid + t*256;
            int row = c>>3, c16 = c&7;
            const __half* src = (row < GBM)
                ? (Ab + (size_t)row*K + i*GBK + c16*8)
                : (Bb + (size_t)(row-GBM)*K + i*GBK + c16*8);
            cp16(stg + row*ROWB + c16*16, src);
        }
        cp_commit();
    };
    load_stage(0); load_stage(1);

    int warp = tid>>5, lane = tid&31;
    int wm = warp&1, wn = warp>>1;
    float acc[4][4][4];
    #pragma unroll
    for(int mi=0;mi<4;mi++) for(int ni=0;ni<4;ni++) for(int d=0;d<4;d++) acc[mi][ni][d]=0.f;

    for (int i=0; i<NK; i++){
        if (i <= NK-2) cp_wait<1>(); else cp_wait<0>();
        __syncthreads();
        uint32_t sA = sbase + (i&1)*STG_BYTES;
        uint32_t sB = sA + GBM*ROWB;
        #pragma unroll
        for (int k16=0; k16<GBK/16; k16++){
            uint32_t a[4][4], b[2][4];
            #pragma unroll
            for(int mi=0;mi<4;mi++){
                int row = wm*64 + mi*16 + (lane&15);
                int col = (k16*16 + (lane>>4)*8)*2;
                ldsm_x4(a[mi][0],a[mi][1],a[mi][2],a[mi][3], sA + row*ROWB + col);
            }
            #pragma unroll
            for(int nj=0;nj<2;nj++){
                int row = wn*32 + nj*16 + ((lane>>4)*8) + (lane&7);
                int col = (k16*16 + ((lane>>3)&1)*8)*2;
                ldsm_x4(b[nj][0],b[nj][1],b[nj][2],b[nj][3], sB + row*ROWB + col);
            }
            #pragma unroll
            for(int mi=0;mi<4;mi++)
                #pragma unroll
                for(int nj=0;nj<2;nj++){
                    mma16816(acc[mi][2*nj][0],acc[mi][2*nj][1],acc[mi][2*nj][2],acc[mi][2*nj][3],
                             a[mi][0],a[mi][1],a[mi][2],a[mi][3], b[nj][0],b[nj][1]);
                    mma16816(acc[mi][2*nj+1][0],acc[mi][2*nj+1][1],acc[mi][2*nj+1][2],acc[mi][2*nj+1][3],
                             a[mi][0],a[mi][1],a[mi][2],a[mi][3], b[nj][2],b[nj][3]);
                }
        }
        __syncthreads();
        if (i + 2 < NK) load_stage(i + 2);
    }

    int mbase = bm*GBM + wm*64;
    int nbase = bn*GBN + wn*32;
    #pragma unroll
    for(int mi=0;mi<4;mi++){
        int r0 = mbase + mi*16 + (lane>>2);
        #pragma unroll
        for(int ni=0;ni<4;ni++){
            int cc = nbase + ni*8 + 2*(lane&3);
            float bv0 = bias[cc], bv1 = bias[cc+1];
            *reinterpret_cast<float2*>(C + (size_t)r0*N + cc) =
                make_float2(acc[mi][ni][0]+bv0, acc[mi][ni][1]+bv1);
            *reinterpret_cast<float2*>(C + (size_t)(r0+8)*N + cc) =
                make_float2(acc[mi][ni][2]+bv0, acc[mi][ni][3]+bv1);
        }
    }
}

// ---------------- fused recurrence + projection (dynamic ticket) ----------------
#define RECUR_CTAS 128
#define PROJ_CTAS  168
#define TOT_CTAS   (RECUR_CTAS+PROJ_CTAS)
#define NT_BM      (SB/GBM)            // 32
#define NT_BN      (VOCAB/GBN)         // 250
#define NT_TILES   (NT_BM*NT_BN)       // 8000
#define F_SMEM     (2*STG_BYTES)       // 73728
#define WOUT_N2    ((int)((size_t)VOCAB*HID/2))

__device__ __forceinline__ void proj_tile(uint32_t sbase, int bm, int bn, int tid,
                                          const __half* __restrict__ Apool,
                                          const __half* __restrict__ Bw,
                                          const float* __restrict__ bias,
                                          float* __restrict__ C){
    const __half* Ab = Apool + (size_t)bm*GBM*HID;
    const __half* Bb = Bw + (size_t)bn*GBN*HID;
    const int NK = HID/GBK;  // 16
    auto load_stage = [&](int i){
        uint32_t stg = sbase + (i&1)*STG_BYTES;
        #pragma unroll
        for (int t=0;t<8;t++){
            int c = tid + t*256;
            int row = c>>3, c16 = c&7;
            const __half* src = (row < GBM)
                ? (Ab + (size_t)row*HID + i*GBK + c16*8)
                : (Bb + (size_t)(row-GBM)*HID + i*GBK + c16*8);
            cp16(stg + row*ROWB + c16*16, src);
        }
        cp_commit();
    };
    load_stage(0); load_stage(1);

    int warp = tid>>5, lane = tid&31;
    int wm = warp&1, wn = warp>>1;
    float acc[4][4][4];
    #pragma unroll
    for(int mi=0;mi<4;mi++) for(int ni=0;ni<4;ni++) for(int d=0;d<4;d++) acc[mi][ni][d]=0.f;

    for (int i=0; i<NK; i++){
        if (i <= NK-2) cp_wait<1>(); else cp_wait<0>();
        __syncthreads();
        uint32_t sA = sbase + (i&1)*STG_BYTES;
        uint32_t sB = sA + GBM*ROWB;
        #pragma unroll
        for (int k16=0; k16<GBK/16; k16++){
            uint32_t a[4][4], b[2][4];
            #pragma unroll
            for(int mi=0;mi<4;mi++){
                int row = wm*64 + mi*16 + (lane&15);
                int col = (k16*16 + (lane>>4)*8)*2;
                ldsm_x4(a[mi][0],a[mi][1],a[mi][2],a[mi][3], sA + row*ROWB + col);
            }
            #pragma unroll
            for(int nj=0;nj<2;nj++){
                int row = wn*32 + nj*16 + ((lane>>4)*8) + (lane&7);
                int col = (k16*16 + ((lane>>3)&1)*8)*2;
                ldsm_x4(b[nj][0],b[nj][1],b[nj][2],b[nj][3], sB + row*ROWB + col);
            }
            #pragma unroll
            for(int mi=0;mi<4;mi++)
                #pragma unroll
                for(int nj=0;nj<2;nj++){
                    mma16816(acc[mi][2*nj][0],acc[mi][2*nj][1],acc[mi][2*nj][2],acc[mi][2*nj][3],
                             a[mi][0],a[mi][1],a[mi][2],a[mi][3], b[nj][0],b[nj][1]);
                    mma16816(acc[mi][2*nj+1][0],acc[mi][2*nj+1][1],acc[mi][2*nj+1][2],acc[mi][2*nj+1][3],
                             a[mi][0],a[mi][1],a[mi][2],a[mi][3], b[nj][2],b[nj][3]);
                }
        }
        __syncthreads();
        if (i + 2 < NK) load_stage(i + 2);
    }

    int mbase = bm*GBM + wm*64;
    int nbase = bn*GBN + wn*32;
    #pragma unroll
    for(int mi=0;mi<4;mi++){
        int r0 = mbase + mi*16 + (lane>>2);
        #pragma unroll
        for(int ni=0;ni<4;ni++){
            int cc = nbase + ni*8 + 2*(lane&3);
            float bv0 = bias[cc], bv1 = bias[cc+1];
            int rr = r0;
            size_t ro = (size_t)((rr&63)*64 + (rr>>6))*VOCAB;
            *reinterpret_cast<float2*>(C + ro + cc) = make_float2(acc[mi][ni][0]+bv0, acc[mi][ni][1]+bv1);
            rr = r0+8;
            ro = (size_t)((rr&63)*64 + (rr>>6))*VOCAB;
            *reinterpret_cast<float2*>(C + ro + cc) = make_float2(acc[mi][ni][2]+bv0, acc[mi][ni][3]+bv1);
        }
    }
}

__device__ __forceinline__ void wait_flag(int need, int tid){
    if (tid == 0){
        while (g_flag < need) __nanosleep(128);
        __threadfence();
    }
    __syncthreads();
}
__device__ __forceinline__ void wait_pcount(int tid){
    if (tid == 0){
        while (g_pcount < PROJ_CTAS) __nanosleep(128);
        __threadfence();
    }
    __syncthreads();
}

__global__ __launch_bounds__(256,2)
void k_fused(const float* __restrict__ w_hh, const float* __restrict__ b_hh,
             const float* __restrict__ hidden,
             const float* __restrict__ w_out_f32, const float* __restrict__ b_out,
             float* __restrict__ out){
    extern __shared__ char smem[];
    __shared__ int s_tix;
    uint32_t sbase = smem_u32(smem);
    int tid = threadIdx.x;
    int cta = blockIdx.x;

    if (cta < RECUR_CTAS){
        // ===== recurrence: j-slice [cta*8, cta*8+8) =====
        __half* sW  = (__half*)smem;                    // 24 x 1032 halfs
        __half* sH  = (__half*)(smem + 49536);          // 64 x 136 halfs
        float*  sGH = (float*)(smem + 66944);           // 64 x 24 f32
        int j0 = cta*8;

        for (int idx = tid; idx < 24*HID; idx += 256){
            int r = idx>>10, k = idx&1023;
            int g = r>>3, jr = r&7;
            sW[r*1032 + k] = __float2half(w_hh[(size_t)(g*HID + j0 + jr)*HID + k]);
        }
        float bh0[2], bh1[2], bh2[2], hold[2];
        #pragma unroll
        for (int t=0;t<2;t++){
            int o = tid + t*256; int b = o>>3, jj = o&7; int j = j0+jj;
            bh0[t]=b_hh[j]; bh1[t]=b_hh[HID+j]; bh2[t]=b_hh[2*HID+j];
            hold[t]=hidden[b*HID + j];
        }
        int warp = tid>>5, lane = tid&31;
        int wm = warp&3, wn = warp>>2;
        int nacc = (wn==0)?2:1;
        __syncthreads();

        for (int s=0; s<SEQ; s++){
            const __half* hb = g_h16[s&1];
            float acc[2][4];
            #pragma unroll
            for(int q=0;q<2;q++) for(int d=0;d<4;d++) acc[q][d]=0.f;

            for (int ch=0; ch<8; ch++){
                __syncthreads();
                #pragma unroll
                for (int i=0;i<4;i++){
                    int lin = tid + i*256;
                    int row = lin>>4, c8 = lin&15;
                    uint4 v = __ldcg(reinterpret_cast<const uint4*>(hb + row*HID + ch*128 + c8*8));
                    *reinterpret_cast<uint4*>(&sH[row*136 + c8*8]) = v;
                }
                __syncthreads();
                #pragma unroll
                for (int k16=0;k16<8;k16++){
                    uint32_t a0,a1,a2,a3;
                    int arow = wm*16 + (lane&15);
                    int acol = k16*16 + (lane>>4)*8;
                    ldsm_x4(a0,a1,a2,a3, smem_u32(&sH[arow*136 + acol]));
                    #pragma unroll
                    for (int q=0;q<2;q++){
                        if (q < nacc){
                            int ni = wn*2 + q;
                            uint32_t b0,b1;
                            int brow = ni*8 + (lane&7);
                            int bcol = ch*128 + k16*16 + ((lane>>3)&1)*8;
                            ldsm_x2(b0,b1, smem_u32(&sW[brow*1032 + bcol]));
                            mma16816(acc[q][0],acc[q][1],acc[q][2],acc[q][3],a0,a1,a2,a3,b0,b1);
                        }
                    }
                }
            }
            {
                int r = wm*16 + (lane>>2);
                #pragma unroll
                for (int q=0;q<2;q++){
                    if (q < nacc){
                        int ni = wn*2 + q;
                        int cc = ni*8 + 2*(lane&3);
                        sGH[r*24 + cc]       = acc[q][0];
                        sGH[r*24 + cc+1]     = acc[q][1];
                        sGH[(r+8)*24 + cc]   = acc[q][2];
                        sGH[(r+8)*24 + cc+1] = acc[q][3];
                    }
                }
            }
            __syncthreads();
            __half* hwr = g_h16[(s+1)&1];
            #pragma unroll
            for (int t=0;t<2;t++){
                int o = tid + t*256; int b = o>>3, jj = o&7; int j = j0+jj;
                const float* gi = g_gi + (size_t)(s*BATCH + b)*H3;
                float ir = gi[j], iz = gi[HID+j], inn = gi[2*HID+j];
                float hr = sGH[b*24+jj]    + bh0[t];
                float hz = sGH[b*24+8+jj]  + bh1[t];
                float hn = sGH[b*24+16+jj] + bh2[t];
                float rg = 1.f/(1.f+__expf(-(ir+hr)));
                float zg = 1.f/(1.f+__expf(-(iz+hz)));
                float ng = tanhf(inn + rg*hn);
                float hnew = (1.f - zg)*ng + zg*hold[t];
                hold[t] = hnew;
                unsigned short hb16 = __half_as_ushort(__float2half(hnew));
                __stcg(reinterpret_cast<unsigned short*>(hwr + b*HID + j), hb16);
                __stcg(reinterpret_cast<unsigned short*>(g_hs + (size_t)(s*BATCH + b)*HID + j), hb16);
            }
            // grid barrier + flag publish; root fences AFTER observing last arrival
            // so all CTAs' released hs stores are ordered before the g_flag store.
            __threadfence();
            __syncthreads();
            if (tid==0){
                unsigned old = g_bar_sense;
                unsigned a = atomicAdd(&g_bar_count, 1u);
                if (a == RECUR_CTAS-1){
                    __threadfence();
                    g_bar_count = 0;
                    g_flag = s+1;
                    __threadfence();
                    atomicExch((unsigned*)&g_bar_sense, old+1u);
                } else {
                    while (g_bar_sense == old) __nanosleep(32);
                }
                __threadfence();
            }
            __syncthreads();
        }
        // ===== join projection ticket pool =====
        wait_pcount(tid);
        for (;;){
            __syncthreads();
            if (tid == 0) s_tix = (int)atomicAdd(&g_ticket, 1u);
            __syncthreads();
            int t = s_tix;
            if (t >= NT_TILES) break;
            int bm = t / NT_BN, bn = t % NT_BN;
            proj_tile(sbase, bm, bn, tid, g_hs, g_wout, b_out, out);
        }
    } else {
        // ===== projection CTAs: convert w_out, then ticket pool (gated) =====
        int pidx = cta - RECUR_CTAS;
        {
            const float2* src = reinterpret_cast<const float2*>(w_out_f32);
            __half2* dst = reinterpret_cast<__half2*>(g_wout);
            for (int i = pidx*256 + tid; i < WOUT_N2; i += PROJ_CTAS*256){
                float2 v = src[i];
                dst[i] = __floats2half2_rn(v.x, v.y);
            }
        }
        __threadfence();
        __syncthreads();
        if (tid == 0) atomicAdd((unsigned*)&g_pcount, 1u);
        wait_pcount(tid);

        for (;;){
            __syncthreads();
            if (tid == 0) s_tix = (int)atomicAdd(&g_ticket, 1u);
            __syncthreads();
            int t = s_tix;
            if (t >= NT_TILES) break;
            int bm = t / NT_BN, bn = t % NT_BN;
            wait_flag(2*bm + 2, tid);
            proj_tile(sbase, bm, bn, tid, g_hs, g_wout, b_out, out);
        }
    }
}

// ---------------- launch ----------------
extern "C" void kernel_launch(void* const* d_in, const int* in_sizes, int n_in,
                              void* d_out, int out_size){
    const int*   x      = (const int*)  d_in[0];
    const float* hidden = (const float*)d_in[1];
    const float* emb    = (const float*)d_in[2];
    const float* w_ih   = (const float*)d_in[3];
    const float* w_hh   = (const float*)d_in[4];
    const float* b_ih   = (const float*)d_in[5];
    const float* b_hh   = (const float*)d_in[6];
    const float* w_out  = (const float*)d_in[7];
    const float* b_out  = (const float*)d_in[8];
    float* out = (float*)d_out;

    __half *pE, *pWih;
    float  *pGi;
    cudaGetSymbolAddress((void**)&pE,    g_E);
    cudaGetSymbolAddress((void**)&pWih,  g_wih);
    cudaGetSymbolAddress((void**)&pGi,   g_gi);

    cudaFuncSetAttribute(k_gemm,  cudaFuncAttributeMaxDynamicSharedMemorySize, G_SMEM);
    cudaFuncSetAttribute(k_fused, cudaFuncAttributeMaxDynamicSharedMemorySize, F_SMEM);

    // merged prep — grid covers the LARGEST task (embed: SB*EMBD/2 threads)
    k_prep<<<(SB*EMBD/2 + 255)/256, 256>>>(x, emb, w_ih, hidden);

    // gi = relu(E) @ w_ih^T + b_ih   (4096 x 3072, K=512)
    k_gemm<<<dim3(SB/GBM, H3/GBN), 256, G_SMEM>>>(pE, pWih, b_ih, pGi, EMBD, H3);

    // fused: recurrence + wout-cvt + ticket-scheduled projection
    k_fused<<<TOT_CTAS, 256, F_SMEM>>>(w_hh, b_hh, hidden, w_out, b_out, out);
}

// round 16
// speedup vs baseline: 1.2113x; 1.0033x over previous
#include <cuda_runtime.h>
#include <cuda_fp16.h>
#include <cstdint>

#define SEQ   64
#define BATCH 64
#define EMBD  512
#define HID   1024
#define VOCAB 32000
#define SB    (SEQ*BATCH)
#define H3    (3*HID)

// ---------------- device scratch ----------------
__device__ __half g_E[SB*EMBD];
__device__ __half g_wih[H3*EMBD];
__device__ __half g_wout[(size_t)VOCAB*HID];
__device__ float  g_gi[(size_t)SB*H3];
__device__ __half g_hs[(size_t)SB*HID];
__device__ __half g_h16[2][BATCH*HID];
__device__ unsigned g_bar_count = 0;
__device__ volatile unsigned g_bar_sense = 0;
__device__ volatile int g_flag = 0;
__device__ volatile unsigned g_pcount = 0;
__device__ unsigned g_ticket = 0;          // proj tiles
__device__ unsigned g_ticket_gi = 0;       // gi tiles
__device__ volatile unsigned g_gi_done[32];// per-bm gi tile counters (target 24)

// ---------------- ptx helpers ----------------
__device__ __forceinline__ uint32_t smem_u32(const void* p){
    return (uint32_t)__cvta_generic_to_shared(p);
}
__device__ __forceinline__ void ldsm_x4(uint32_t&a0,uint32_t&a1,uint32_t&a2,uint32_t&a3,uint32_t addr){
    asm volatile("ldmatrix.sync.aligned.m8n8.x4.shared.b16 {%0,%1,%2,%3},[%4];"
                 :"=r"(a0),"=r"(a1),"=r"(a2),"=r"(a3):"r"(addr));
}
__device__ __forceinline__ void ldsm_x2(uint32_t&b0,uint32_t&b1,uint32_t addr){
    asm volatile("ldmatrix.sync.aligned.m8n8.x2.shared.b16 {%0,%1},[%2];"
                 :"=r"(b0),"=r"(b1):"r"(addr));
}
__device__ __forceinline__ void mma16816(float&d0,float&d1,float&d2,float&d3,
                                         uint32_t a0,uint32_t a1,uint32_t a2,uint32_t a3,
                                         uint32_t b0,uint32_t b1){
    asm volatile("mma.sync.aligned.m16n8k16.row.col.f32.f16.f16.f32 "
                 "{%0,%1,%2,%3},{%4,%5,%6,%7},{%8,%9},{%0,%1,%2,%3};"
                 :"+f"(d0),"+f"(d1),"+f"(d2),"+f"(d3)
                 :"r"(a0),"r"(a1),"r"(a2),"r"(a3),"r"(b0),"r"(b1));
}
__device__ __forceinline__ void cp16(uint32_t saddr, const void* g){
    asm volatile("cp.async.cg.shared.global [%0],[%1],16;"::"r"(saddr),"l"(g));
}
__device__ __forceinline__ void cp_commit(){ asm volatile("cp.async.commit_group;"); }
template<int N> __device__ __forceinline__ void cp_wait(){ asm volatile("cp.async.wait_group %0;"::"n"(N)); }

// ---------------- merged prep kernel ----------------
// Grid covers the LARGEST task: embed = SB*EMBD/2 = 1,048,576 threads.
__global__ void k_prep(const int* __restrict__ x, const float* __restrict__ emb,
                       const float* __restrict__ w_ih, const float* __restrict__ hidden){
    int i = blockIdx.x*blockDim.x + threadIdx.x;
    if (i < H3*EMBD/2){
        float2 v = reinterpret_cast<const float2*>(w_ih)[i];
        reinterpret_cast<__half2*>(g_wih)[i] = __floats2half2_rn(v.x, v.y);
    }
    if (i < SB*EMBD/2){
        int row = i/(EMBD/2), cp = i%(EMBD/2);
        int s = row>>6, b = row&63;
        int tok = (s==0) ? 2 : x[(s-1)*BATCH + b];
        float2 v = reinterpret_cast<const float2*>(emb + (size_t)tok*EMBD)[cp];
        float a0 = (tok==0)?0.f:fmaxf(v.x,0.f);
        float a1 = (tok==0)?0.f:fmaxf(v.y,0.f);
        reinterpret_cast<__half2*>(g_E)[i] = __floats2half2_rn(a0, a1);
    }
    if (i < BATCH*HID) g_h16[0][i] = __float2half(hidden[i]);
    if (i < 32) g_gi_done[i] = 0;
    if (i == 0){ g_bar_count = 0; g_bar_sense = 0; g_flag = 0; g_pcount = 0;
                 g_ticket = 0; g_ticket_gi = 0; }
}

// ---------------- generic HMMA tile: C[128 rows, 128 cols] += A@Bw^T + bias ----------------
#define GBM 128
#define GBN 128
#define GBK 64
#define ROWB 144
#define STG_ROWS (GBM+GBN)           // 256
#define STG_BYTES (STG_ROWS*ROWB)    // 36864
#define F_SMEM (2*STG_BYTES)         // 73728

template<bool PERM>
__device__ __forceinline__ void gemm_tile(uint32_t sbase, int bm, int bn, int tid,
                                          const __half* __restrict__ Apool, int K,
                                          const __half* __restrict__ Bw,
                                          const float* __restrict__ bias,
                                          float* __restrict__ C, int N){
    const __half* Ab = Apool + (size_t)bm*GBM*K;
    const __half* Bb = Bw + (size_t)bn*GBN*K;
    const int NK = K/GBK;
    auto load_stage = [&](int i){
        uint32_t stg = sbase + (i&1)*STG_BYTES;
        #pragma unroll
        for (int t=0;t<8;t++){
            int c = tid + t*256;
            int row = c>>3, c16 = c&7;
            const __half* src = (row < GBM)
                ? (Ab + (size_t)row*K + i*GBK + c16*8)
                : (Bb + (size_t)(row-GBM)*K + i*GBK + c16*8);
            cp16(stg + row*ROWB + c16*16, src);
        }
        cp_commit();
    };
    load_stage(0); load_stage(1);

    int warp = tid>>5, lane = tid&31;
    int wm = warp&1, wn = warp>>1;
    float acc[4][4][4];
    #pragma unroll
    for(int mi=0;mi<4;mi++) for(int ni=0;ni<4;ni++) for(int d=0;d<4;d++) acc[mi][ni][d]=0.f;

    for (int i=0; i<NK; i++){
        if (i <= NK-2) cp_wait<1>(); else cp_wait<0>();
        __syncthreads();
        uint32_t sA = sbase + (i&1)*STG_BYTES;
        uint32_t sB = sA + GBM*ROWB;
        #pragma unroll
        for (int k16=0; k16<GBK/16; k16++){
            uint32_t a[4][4], b[2][4];
            #pragma unroll
            for(int mi=0;mi<4;mi++){
                int row = wm*64 + mi*16 + (lane&15);
                int col = (k16*16 + (lane>>4)*8)*2;
                ldsm_x4(a[mi][0],a[mi][1],a[mi][2],a[mi][3], sA + row*ROWB + col);
            }
            #pragma unroll
            for(int nj=0;nj<2;nj++){
                int row = wn*32 + nj*16 + ((lane>>4)*8) + (lane&7);
                int col = (k16*16 + ((lane>>3)&1)*8)*2;
                ldsm_x4(b[nj][0],b[nj][1],b[nj][2],b[nj][3], sB + row*ROWB + col);
            }
            #pragma unroll
            for(int mi=0;mi<4;mi++)
                #pragma unroll
                for(int nj=0;nj<2;nj++){
                    mma16816(acc[mi][2*nj][0],acc[mi][2*nj][1],acc[mi][2*nj][2],acc[mi][2*nj][3],
                             a[mi][0],a[mi][1],a[mi][2],a[mi][3], b[nj][0],b[nj][1]);
                    mma16816(acc[mi][2*nj+1][0],acc[mi][2*nj+1][1],acc[mi][2*nj+1][2],acc[mi][2*nj+1][3],
                             a[mi][0],a[mi][1],a[mi][2],a[mi][3], b[nj][2],b[nj][3]);
                }
        }
        __syncthreads();
        if (i + 2 < NK) load_stage(i + 2);
    }

    int mbase = bm*GBM + wm*64;
    int nbase = bn*GBN + wn*32;
    #pragma unroll
    for(int mi=0;mi<4;mi++){
        int r0 = mbase + mi*16 + (lane>>2);
        #pragma unroll
        for(int ni=0;ni<4;ni++){
            int cc = nbase + ni*8 + 2*(lane&3);
            float bv0 = bias[cc], bv1 = bias[cc+1];
            int rr = r0;
            size_t ro = PERM ? (size_t)((rr&63)*64 + (rr>>6))*N : (size_t)rr*N;
            *reinterpret_cast<float2*>(C + ro + cc) = make_float2(acc[mi][ni][0]+bv0, acc[mi][ni][1]+bv1);
            rr = r0+8;
            ro = PERM ? (size_t)((rr&63)*64 + (rr>>6))*N : (size_t)rr*N;
            *reinterpret_cast<float2*>(C + ro + cc) = make_float2(acc[mi][ni][2]+bv0, acc[mi][ni][3]+bv1);
        }
    }
}

// ---------------- fused: gi GEMM + recurrence + wout cvt + projection ----------------
#define RECUR_CTAS 128
#define PROJ_CTAS  168
#define TOT_CTAS   (RECUR_CTAS+PROJ_CTAS)
#define NT_BM      (SB/GBM)            // 32
#define NT_BN      (VOCAB/GBN)         // 250
#define NT_TILES   (NT_BM*NT_BN)       // 8000
#define GI_BN      (H3/GBN)            // 24
#define GI_TILES   (NT_BM*GI_BN)       // 768
#define WOUT_N2    ((int)((size_t)VOCAB*HID/2))

__device__ __forceinline__ void wait_flag(int need, int tid){
    if (tid == 0){
        while (g_flag < need) __nanosleep(128);
        __threadfence();
    }
    __syncthreads();
}
__device__ __forceinline__ void wait_pcount(int tid){
    if (tid == 0){
        while (g_pcount < PROJ_CTAS) __nanosleep(128);
        __threadfence();
    }
    __syncthreads();
}

__global__ __launch_bounds__(256,2)
void k_fused(const float* __restrict__ w_hh, const float* __restrict__ b_hh,
             const float* __restrict__ hidden,
             const float* __restrict__ w_out_f32, const float* __restrict__ b_out,
             const float* __restrict__ b_ih,
             float* __restrict__ out){
    extern __shared__ char smem[];
    __shared__ int s_tix;
    uint32_t sbase = smem_u32(smem);
    int tid = threadIdx.x;
    int cta = blockIdx.x;

    if (cta < RECUR_CTAS){
        // ===== recurrence: j-slice [cta*8, cta*8+8) =====
        __half* sW  = (__half*)smem;                    // 24 x 1032 halfs
        __half* sH  = (__half*)(smem + 49536);          // 64 x 136 halfs
        float*  sGH = (float*)(smem + 66944);           // 64 x 24 f32
        int j0 = cta*8;

        for (int idx = tid; idx < 24*HID; idx += 256){
            int r = idx>>10, k = idx&1023;
            int g = r>>3, jr = r&7;
            sW[r*1032 + k] = __float2half(w_hh[(size_t)(g*HID + j0 + jr)*HID + k]);
        }
        float bh0[2], bh1[2], bh2[2], hold[2];
        #pragma unroll
        for (int t=0;t<2;t++){
            int o = tid + t*256; int b = o>>3, jj = o&7; int j = j0+jj;
            bh0[t]=b_hh[j]; bh1[t]=b_hh[HID+j]; bh2[t]=b_hh[2*HID+j];
            hold[t]=hidden[b*HID + j];
        }
        int warp = tid>>5, lane = tid&31;
        int wm = warp&3, wn = warp>>2;
        int nacc = (wn==0)?2:1;
        __syncthreads();

        for (int s=0; s<SEQ; s++){
            // gate on gi availability for this step's rows (bm = s/2)
            if ((s&1)==0){
                if (tid == 0){
                    while (g_gi_done[s>>1] < (unsigned)GI_BN) __nanosleep(64);
                    __threadfence();
                }
                __syncthreads();
            }
            const __half* hb = g_h16[s&1];
            float acc[2][4];
            #pragma unroll
            for(int q=0;q<2;q++) for(int d=0;d<4;d++) acc[q][d]=0.f;

            for (int ch=0; ch<8; ch++){
                __syncthreads();
                #pragma unroll
                for (int i=0;i<4;i++){
                    int lin = tid + i*256;
                    int row = lin>>4, c8 = lin&15;
                    uint4 v = __ldcg(reinterpret_cast<const uint4*>(hb + row*HID + ch*128 + c8*8));
                    *reinterpret_cast<uint4*>(&sH[row*136 + c8*8]) = v;
                }
                __syncthreads();
                #pragma unroll
                for (int k16=0;k16<8;k16++){
                    uint32_t a0,a1,a2,a3;
                    int arow = wm*16 + (lane&15);
                    int acol = k16*16 + (lane>>4)*8;
                    ldsm_x4(a0,a1,a2,a3, smem_u32(&sH[arow*136 + acol]));
                    #pragma unroll
                    for (int q=0;q<2;q++){
                        if (q < nacc){
                            int ni = wn*2 + q;
                            uint32_t b0,b1;
                            int brow = ni*8 + (lane&7);
                            int bcol = ch*128 + k16*16 + ((lane>>3)&1)*8;
                            ldsm_x2(b0,b1, smem_u32(&sW[brow*1032 + bcol]));
                            mma16816(acc[q][0],acc[q][1],acc[q][2],acc[q][3],a0,a1,a2,a3,b0,b1);
                        }
                    }
                }
            }
            {
                int r = wm*16 + (lane>>2);
                #pragma unroll
                for (int q=0;q<2;q++){
                    if (q < nacc){
                        int ni = wn*2 + q;
                        int cc = ni*8 + 2*(lane&3);
                        sGH[r*24 + cc]       = acc[q][0];
                        sGH[r*24 + cc+1]     = acc[q][1];
                        sGH[(r+8)*24 + cc]   = acc[q][2];
                        sGH[(r+8)*24 + cc+1] = acc[q][3];
                    }
                }
            }
            __syncthreads();
            __half* hwr = g_h16[(s+1)&1];
            #pragma unroll
            for (int t=0;t<2;t++){
                int o = tid + t*256; int b = o>>3, jj = o&7; int j = j0+jj;
                const float* gi = g_gi + (size_t)(s*BATCH + b)*H3;
                float ir = gi[j], iz = gi[HID+j], inn = gi[2*HID+j];
                float hr = sGH[b*24+jj]    + bh0[t];
                float hz = sGH[b*24+8+jj]  + bh1[t];
                float hn = sGH[b*24+16+jj] + bh2[t];
                float rg = 1.f/(1.f+__expf(-(ir+hr)));
                float zg = 1.f/(1.f+__expf(-(iz+hz)));
                float ng = tanhf(inn + rg*hn);
                float hnew = (1.f - zg)*ng + zg*hold[t];
                hold[t] = hnew;
                unsigned short hb16 = __half_as_ushort(__float2half(hnew));
                __stcg(reinterpret_cast<unsigned short*>(hwr + b*HID + j), hb16);
                __stcg(reinterpret_cast<unsigned short*>(g_hs + (size_t)(s*BATCH + b)*HID + j), hb16);
            }
            // grid barrier + flag publish (root fences after last arrival)
            __threadfence();
            __syncthreads();
            if (tid==0){
                unsigned old = g_bar_sense;
                unsigned a = atomicAdd(&g_bar_count, 1u);
                if (a == RECUR_CTAS-1){
                    __threadfence();
                    g_bar_count = 0;
                    g_flag = s+1;
                    __threadfence();
                    atomicExch((unsigned*)&g_bar_sense, old+1u);
                } else {
                    while (g_bar_sense == old) __nanosleep(32);
                }
                __threadfence();
            }
            __syncthreads();
        }
        // ===== join projection ticket pool =====
        wait_pcount(tid);
        for (;;){
            __syncthreads();
            if (tid == 0) s_tix = (int)atomicAdd(&g_ticket, 1u);
            __syncthreads();
            int t = s_tix;
            if (t >= NT_TILES) break;
            int bm = t / NT_BN, bn = t % NT_BN;
            gemm_tile<true>(sbase, bm, bn, tid, g_hs, HID, g_wout, b_out, out, VOCAB);
        }
    } else {
        // ===== proj CTAs: gi tiles -> wout cvt -> proj pool =====
        int pidx = cta - RECUR_CTAS;
        // phase 1: gi GEMM tiles (bm-major so early steps unblock first)
        for (;;){
            __syncthreads();
            if (tid == 0) s_tix = (int)atomicAdd(&g_ticket_gi, 1u);
            __syncthreads();
            int t = s_tix;
            if (t >= GI_TILES) break;
            int bm = t / GI_BN, bn = t % GI_BN;
            gemm_tile<false>(sbase, bm, bn, tid, g_E, EMBD, g_wih, b_ih, g_gi, H3);
            __syncthreads();               // all epilogue stores issued
            if (tid == 0){
                __threadfence();           // order gi stores before the done-count
                atomicAdd((unsigned*)&g_gi_done[bm], 1u);
            }
        }
        // phase 2: wout fp32->fp16
        {
            const float2* src = reinterpret_cast<const float2*>(w_out_f32);
            __half2* dst = reinterpret_cast<__half2*>(g_wout);
            for (int i = pidx*256 + tid; i < WOUT_N2; i += PROJ_CTAS*256){
                float2 v = src[i];
                dst[i] = __floats2half2_rn(v.x, v.y);
            }
        }
        __threadfence();
        __syncthreads();
        if (tid == 0) atomicAdd((unsigned*)&g_pcount, 1u);
        wait_pcount(tid);
        // phase 3: proj pool (gated on recurrence progress)
        for (;;){
            __syncthreads();
            if (tid == 0) s_tix = (int)atomicAdd(&g_ticket, 1u);
            __syncthreads();
            int t = s_tix;
            if (t >= NT_TILES) break;
            int bm = t / NT_BN, bn = t % NT_BN;
            wait_flag(2*bm + 2, tid);
            gemm_tile<true>(sbase, bm, bn, tid, g_hs, HID, g_wout, b_out, out, VOCAB);
        }
    }
}

// ---------------- launch ----------------
extern "C" void kernel_launch(void* const* d_in, const int* in_sizes, int n_in,
                              void* d_out, int out_size){
    const int*   x      = (const int*)  d_in[0];
    const float* hidden = (const float*)d_in[1];
    const float* emb    = (const float*)d_in[2];
    const float* w_ih   = (const float*)d_in[3];
    const float* w_hh   = (const float*)d_in[4];
    const float* b_ih   = (const float*)d_in[5];
    const float* b_hh   = (const float*)d_in[6];
    const float* w_out  = (const float*)d_in[7];
    const float* b_out  = (const float*)d_in[8];
    float* out = (float*)d_out;

    cudaFuncSetAttribute(k_fused, cudaFuncAttributeMaxDynamicSharedMemorySize, F_SMEM);

    // prep: wih cvt + embed + h0 + control resets (grid covers embed)
    k_prep<<<(SB*EMBD/2 + 255)/256, 256>>>(x, emb, w_ih, hidden);

    // fused: gi GEMM + recurrence + wout-cvt + ticket-scheduled projection
    k_fused<<<TOT_CTAS, 256, F_SMEM>>>(w_hh, b_hh, hidden, w_out, b_out, b_ih, out);
}